// round 15
// baseline (speedup 1.0000x reference)
#include <cuda_runtime.h>
#include <cuda_fp16.h>
#include <cstdint>

#define B_     8
#define N_     4096
#define D_     1024
#define EMB_   64
#define CLN_   10
#define TILE_M 64
#define KC_    64
#define NCHUNK (D_ / KC_)          // 16
#define NTHR   256                 // 4 consumer + 4 producer warps
#define NCTA_X (N_ / TILE_M)       // 64 CTAs per batch
#define PSTRIDE 656
#define NSTAGE 3

// named barrier ids: FULL = 1+si, EMPTY = 4+si
#define BAR_FULL(si)  (1 + (si))
#define BAR_EMPTY(si) (4 + (si))

// ---------------- device scratch (allocation-free rule) ----------------
__device__ float g_part[B_ * NCTA_X * PSTRIDE];
__device__ int   g_done[B_];                      // zero-init; self-resetting
__device__ __align__(16) __half g_W1hi[EMB_ * D_];
__device__ __align__(16) __half g_W1lo[EMB_ * D_];

// ---------------- dynamic smem layout (bytes) ----------------
#define SM_B1S    0                // 64 f
#define SM_LABS   256              // 64 int
#define SM_CSUM   512              // 2 x 640 f -> ends 5632
#define SM_BUF    6144
// stage: Ahi 8K | Alo 8K | Bhi 8K | Blo 8K   (64 rows x 128B each)
#define ALO_OFF   8192
#define BHI_OFF   16384
#define BLO_OFF   24576
#define STAGE_SZ  32768
#define SMEM_TOTAL (SM_BUF + NSTAGE * STAGE_SZ)   // 104448 -> 2 CTAs/SM

__device__ __forceinline__ uint32_t smem_u32(const void* p) {
    uint32_t a;
    asm("{ .reg .u64 t; cvta.to.shared.u64 t, %1; cvt.u32.u64 %0, t; }" : "=r"(a) : "l"(p));
    return a;
}
__device__ __forceinline__ uint32_t sw128(uint32_t o) { return o ^ ((o >> 3) & 0x70); }

__device__ __forceinline__ void ldmx4(uint32_t* r, uint32_t addr) {
    asm volatile("ldmatrix.sync.aligned.m8n8.x4.shared.b16 {%0,%1,%2,%3}, [%4];"
                 : "=r"(r[0]), "=r"(r[1]), "=r"(r[2]), "=r"(r[3]) : "r"(addr));
}
__device__ __forceinline__ void mma16816(float* c, const uint32_t* a, uint32_t b0, uint32_t b1) {
    asm volatile("mma.sync.aligned.m16n8k16.row.col.f32.f16.f16.f32 "
                 "{%0,%1,%2,%3}, {%4,%5,%6,%7}, {%8,%9}, {%0,%1,%2,%3};"
                 : "+f"(c[0]), "+f"(c[1]), "+f"(c[2]), "+f"(c[3])
                 : "r"(a[0]), "r"(a[1]), "r"(a[2]), "r"(a[3]), "r"(b0), "r"(b1));
}
__device__ __forceinline__ void cpasync16(uint32_t saddr, const void* gaddr) {
    asm volatile("cp.async.cg.shared.global [%0], [%1], 16;" :: "r"(saddr), "l"(gaddr));
}
__device__ __forceinline__ void bar_sync(int id) {
    asm volatile("bar.sync %0, %1;" :: "r"(id), "r"(NTHR) : "memory");
}
__device__ __forceinline__ void bar_arrive(int id) {
    asm volatile("bar.arrive %0, %1;" :: "r"(id), "r"(NTHR) : "memory");
}

// ---------------------------------------------------------------------------
// Kernel 0: split-convert W1 to fp16 hi/lo
// ---------------------------------------------------------------------------
__global__ void init_kernel(const float* __restrict__ W1) {
    int i4 = blockIdx.x * 256 + threadIdx.x;
    float4 v = *(const float4*)(W1 + (size_t)i4 * 4);
    __half2 h0 = __floats2half2_rn(v.x, v.y);
    __half2 h1 = __floats2half2_rn(v.z, v.w);
    float2 f0 = __half22float2(h0), f1 = __half22float2(h1);
    __half2 l0 = __floats2half2_rn(v.x - f0.x, v.y - f0.y);
    __half2 l1 = __floats2half2_rn(v.z - f1.x, v.w - f1.y);
    uint2 hv, lv;
    hv.x = *(uint32_t*)&h0; hv.y = *(uint32_t*)&h1;
    lv.x = *(uint32_t*)&l0; lv.y = *(uint32_t*)&l1;
    *(uint2*)(g_W1hi + (size_t)i4 * 4) = hv;
    *(uint2*)(g_W1lo + (size_t)i4 * 4) = lv;
}

// ---------------------------------------------------------------------------
// Fused kernel, WARP-SPECIALIZED, 3-stage ring + producer LDG pipeline:
//   warps 0-3 (consumers): bar.sync(full) -> LDSM+MMA only -> bar.arrive(empty)
//   warps 4-7 (producers): B cp.async + A cvt/STS from prefetched regs;
//                          LDG for chunk c+1 issued BEFORE the empty-wait.
// 3-term split D = Ahi*Bhi + Ahi*Blo + Alo*Bhi; last CTA per batch runs head.
// ---------------------------------------------------------------------------
__global__ void __launch_bounds__(NTHR, 2)
fused_kernel(const float* __restrict__ data,
             const int*   __restrict__ labels,
             const float* __restrict__ b1,
             const float* __restrict__ Wa1, const float* __restrict__ ba1,
             const float* __restrict__ Wa2, const float* __restrict__ ba2,
             const float* __restrict__ Wf1, const float* __restrict__ bf1,
             const float* __restrict__ Wf2, const float* __restrict__ bf2,
             float* __restrict__ out) {
    extern __shared__ char smem[];
    const uint32_t sb = smem_u32(smem);
    const int tid  = threadIdx.x;
    const int warp = tid >> 5;
    const int lane = tid & 31;
    const int b    = blockIdx.y;
    const int bx   = blockIdx.x;
    const int p0   = bx * TILE_M;

    float* b1s  = (float*)(smem + SM_B1S);
    int*   labs = (int*)  (smem + SM_LABS);
    float* csum = (float*)(smem + SM_CSUM);

    if (tid < EMB_)   b1s[tid]  = b1[tid];
    if (tid < TILE_M) labs[tid] = labels[b * N_ + p0 + tid];
    for (int i = tid; i < 2 * CLN_ * EMB_; i += NTHR) csum[i] = 0.0f;
    __syncthreads();

    float acc[8][4];
#pragma unroll
    for (int nt = 0; nt < 8; nt++)
#pragma unroll
        for (int i = 0; i < 4; i++) acc[nt][i] = 0.0f;

    if (warp >= 4) {
        // ================= PRODUCER warps (4-7) =================
        const int tp  = tid - 128;            // 0..127
        const int a_r = tp >> 4;              // A row base (+l*8)
        const int a_q = tp & 15;
        const int b_r = tp >> 3;              // B row base (+l*16)
        const int b_q = tp & 7;
        const float* dbase = data + (size_t)(b * N_ + p0) * D_;

        float4 pre[8];
        // prefetch chunk 0
#pragma unroll
        for (int l = 0; l < 8; l++)
            pre[l] = *(const float4*)(dbase + (size_t)(a_r + l * 8) * D_ + a_q * 4);

        for (int c = 0; c < NCHUNK; c++) {
            const int si = c % NSTAGE;
            if (c >= NSTAGE) bar_sync(BAR_EMPTY(si));    // consumers freed stage

            const uint32_t bufa = sb + SM_BUF + si * STAGE_SZ;
            char* buf = smem + SM_BUF + si * STAGE_SZ;
            const int kc = c * KC_;

            // B: cp.async from pre-split weights
#pragma unroll
            for (int l = 0; l < 4; l++) {
                int r = b_r + l * 16;
                uint32_t sw = sw128((uint32_t)(r * 128 + b_q * 16));
                cpasync16(bufa + BHI_OFF + sw, g_W1hi + (size_t)r * D_ + kc + b_q * 8);
                cpasync16(bufa + BLO_OFF + sw, g_W1lo + (size_t)r * D_ + kc + b_q * 8);
            }
            asm volatile("cp.async.commit_group;");

            // A: split-cvt prefetched regs -> STS
#pragma unroll
            for (int l = 0; l < 8; l++) {
                int r = a_r + l * 8;
                float4 x = pre[l];
                __half2 h0 = __floats2half2_rn(x.x, x.y);
                __half2 h1 = __floats2half2_rn(x.z, x.w);
                float2 f0 = __half22float2(h0), f1 = __half22float2(h1);
                __half2 l0 = __floats2half2_rn(x.x - f0.x, x.y - f0.y);
                __half2 l1 = __floats2half2_rn(x.z - f1.x, x.w - f1.y);
                uint32_t sw = sw128((uint32_t)(r * 128 + a_q * 8));
                uint2 hv, lv;
                hv.x = *(uint32_t*)&h0; hv.y = *(uint32_t*)&h1;
                lv.x = *(uint32_t*)&l0; lv.y = *(uint32_t*)&l1;
                *(uint2*)(buf + sw)           = hv;
                *(uint2*)(buf + ALO_OFF + sw) = lv;
            }

            // LDG for next chunk flies during wait_group + barrier + consume
            if (c + 1 < NCHUNK) {
                const int kc1 = (c + 1) * KC_;
#pragma unroll
                for (int l = 0; l < 8; l++)
                    pre[l] = *(const float4*)(dbase + (size_t)(a_r + l * 8) * D_ + kc1 + a_q * 4);
            }

            asm volatile("cp.async.wait_group 0;");
            asm volatile("membar.cta;");                 // order STS before arrive
            bar_arrive(BAR_FULL(si));
        }
    } else {
        // ================= CONSUMER warps (0-3) =================
        const uint32_t arow  = (uint32_t)(warp * 16 + (lane & 15));
        const uint32_t acolb = (uint32_t)((lane >> 4) * 16);
        const uint32_t brow8 = (uint32_t)(((lane >> 4) & 1) * 8 + (lane & 7));
        const uint32_t bkb   = (uint32_t)(((lane >> 3) & 1) * 16);

        for (int c = 0; c < NCHUNK; c++) {
            const int si = c % NSTAGE;
            bar_sync(BAR_FULL(si));                      // stage ready
            const uint32_t st = sb + SM_BUF + si * STAGE_SZ;
#pragma unroll
            for (int ks = 0; ks < 4; ks++) {
                uint32_t ah[4], al[4];
                uint32_t aoff = sw128(arow * 128 + (uint32_t)(ks * 32) + acolb);
                ldmx4(ah, st + aoff);
                ldmx4(al, st + ALO_OFF + aoff);
#pragma unroll
                for (int j = 0; j < 4; j++) {
                    uint32_t bh[4], bl[4];
                    uint32_t boff = sw128((uint32_t)(j * 16 + (int)brow8) * 128 +
                                          (uint32_t)(ks * 32) + bkb);
                    ldmx4(bh, st + BHI_OFF + boff);
                    ldmx4(bl, st + BLO_OFF + boff);
                    mma16816(acc[2 * j],     ah, bh[0], bh[1]);
                    mma16816(acc[2 * j],     ah, bl[0], bl[1]);
                    mma16816(acc[2 * j],     al, bh[0], bh[1]);
                    mma16816(acc[2 * j + 1], ah, bh[2], bh[3]);
                    mma16816(acc[2 * j + 1], ah, bl[2], bl[3]);
                    mma16816(acc[2 * j + 1], al, bh[2], bh[3]);
                }
            }
            bar_arrive(BAR_EMPTY(si));                   // stage free
        }
    }
    __syncthreads();

    // ---- epilogue: bias + ReLU -> e-tile (64 x 66, reuse stage region) ----
    float* etile = (float*)(smem + SM_BUF);
    if (warp < 4) {
        int r0 = warp * 16 + (lane >> 2);
        int cq = 2 * (lane & 3);
#pragma unroll
        for (int nt = 0; nt < 8; nt++) {
            int col = nt * 8 + cq;
            float bv0 = b1s[col], bv1 = b1s[col + 1];
            etile[r0 * 66 + col]           = fmaxf(acc[nt][0] + bv0, 0.0f);
            etile[r0 * 66 + col + 1]       = fmaxf(acc[nt][1] + bv1, 0.0f);
            etile[(r0 + 8) * 66 + col]     = fmaxf(acc[nt][2] + bv0, 0.0f);
            etile[(r0 + 8) * 66 + col + 1] = fmaxf(acc[nt][3] + bv1, 0.0f);
        }
    }
    __syncthreads();

    if (tid < 128) {   // split-row segment reduction, no atomics
        int half = tid >> 6;
        int e    = tid & 63;
        float* cs = csum + half * (CLN_ * EMB_);
        int rbase = half * 32;
        for (int r = 0; r < 32; r++) {
            int row = rbase + r;
            cs[labs[row] * EMB_ + e] += etile[row * 66 + e];
        }
    }
    __syncthreads();

    float* prow = g_part + ((size_t)b * NCTA_X + bx) * PSTRIDE;
    for (int i = tid; i < CLN_ * EMB_; i += NTHR)
        prow[i] = csum[i] + csum[CLN_ * EMB_ + i];
    if (tid < CLN_) {
        int cnt = 0;
        for (int r = 0; r < TILE_M; r++) cnt += (labs[r] == tid);
        prow[640 + tid] = (float)cnt;
    }
    __threadfence();
    __syncthreads();

    // ---- last CTA of this batch runs the head ----
    __shared__ int s_last;
    if (tid == 0) s_last = (atomicAdd(&g_done[b], 1) == NCTA_X - 1) ? 1 : 0;
    __syncthreads();
    if (!s_last) return;
    __threadfence();

    float* hc    = (float*)(smem + SM_BUF);
    float* h     = hc + 656;
    float* u     = h + 640;
    float* score = u + 320;
    float* Avec  = score + 16;
    float* mask  = Avec + 16;
    float* Mv    = mask + 16;
    float* f     = Mv + 64;

    for (int i = tid; i < 650; i += NTHR) {
        float s = 0.0f;
        const float* base = g_part + (size_t)b * NCTA_X * PSTRIDE + i;
#pragma unroll
        for (int j = 0; j < NCTA_X; j++) s += base[j * PSTRIDE];
        hc[i] = s;
    }
    __syncthreads();

    if (tid < EMB_) {
        for (int c = 0; c < CLN_; c++)
            h[c * EMB_ + tid] = hc[c * EMB_ + tid] / fmaxf(hc[640 + c], 1.0f);
    }
    if (tid < CLN_) mask[tid] = (hc[640 + tid] > 0.0f) ? 1.0f : 0.0f;
    __syncthreads();

    if (tid < 32) {
        for (int c = 0; c < CLN_; c++) {
            float s = ba1[tid];
            for (int e = 0; e < EMB_; e++) s += h[c * EMB_ + e] * Wa1[tid * EMB_ + e];
            u[c * 32 + tid] = tanhf(s);
        }
    }
    __syncthreads();

    if (tid < CLN_) {
        float s = ba2[0];
        for (int k = 0; k < 32; k++) s += u[tid * 32 + k] * Wa2[k];
        score[tid] = s;
    }
    __syncthreads();

    if (tid == 0) {
        float xmax = -1e30f;
        for (int c = 0; c < CLN_; c++) {
            float xm = score[c] * mask[c] + (1.0f - 1.0f / (mask[c] + 1e-5f));
            xmax = fmaxf(xmax, xm);
        }
        float ssum = 0.0f;
        for (int c = 0; c < CLN_; c++) {
            float ex = expf(score[c] - xmax) * mask[c];
            Avec[c] = ex;
            ssum += ex;
        }
        for (int c = 0; c < CLN_; c++) Avec[c] /= ssum;
    }
    __syncthreads();

    if (tid < EMB_) {
        float m = 0.0f;
        for (int c = 0; c < CLN_; c++) m += Avec[c] * h[c * EMB_ + tid];
        Mv[tid] = m;
    }
    __syncthreads();

    if (tid < 32) {
        float s = bf1[tid];
        for (int e = 0; e < EMB_; e++) s += Mv[e] * Wf1[tid * EMB_ + e];
        f[tid] = fmaxf(s, 0.0f);
    }
    __syncthreads();

    if (tid == 0) {
        float s = bf2[0];
        for (int k = 0; k < 32; k++) s += f[k] * Wf2[k];
        out[b] = s;
        g_done[b] = 0;      // reset for next graph replay
    }
}

// ---------------------------------------------------------------------------
extern "C" void kernel_launch(void* const* d_in, const int* in_sizes, int n_in,
                              void* d_out, int out_size) {
    const float* data   = (const float*)d_in[0];
    const int*   labels = (const int*)  d_in[1];
    const float* W1     = (const float*)d_in[2];
    const float* b1     = (const float*)d_in[3];
    const float* Wa1    = (const float*)d_in[4];
    const float* ba1    = (const float*)d_in[5];
    const float* Wa2    = (const float*)d_in[6];
    const float* ba2    = (const float*)d_in[7];
    const float* Wf1    = (const float*)d_in[8];
    const float* bf1    = (const float*)d_in[9];
    const float* Wf2    = (const float*)d_in[10];
    const float* bf2    = (const float*)d_in[11];

    cudaFuncSetAttribute(fused_kernel, cudaFuncAttributeMaxDynamicSharedMemorySize,
                         SMEM_TOTAL);

    init_kernel<<<64, 256>>>(W1);
    fused_kernel<<<dim3(NCTA_X, B_), NTHR, SMEM_TOTAL>>>(
        data, labels, b1, Wa1, ba1, Wa2, ba2, Wf1, bf1, Wf2, bf2,
        (float*)d_out);
}

// round 16
// speedup vs baseline: 1.0485x; 1.0485x over previous
#include <cuda_runtime.h>
#include <cuda_fp16.h>
#include <cstdint>

#define B_     8
#define N_     4096
#define D_     1024
#define EMB_   64
#define CLN_   10
#define TILE_M 64
#define KC_    64
#define NCHUNK (D_ / KC_)          // 16
#define NTHR   256                 // 4 consumer + 4 producer warps
#define NCTA_X (N_ / TILE_M)       // 64 CTAs per batch
#define PSTRIDE 656

// named barrier ids
#define BAR_FULL0  1
#define BAR_FULL1  2
#define BAR_EMPTY0 3
#define BAR_EMPTY1 4

// ---------------- device scratch (allocation-free rule) ----------------
__device__ float g_part[B_ * NCTA_X * PSTRIDE];
__device__ int   g_done[B_];                      // zero-init; self-resetting
__device__ __align__(16) __half g_W1hi[EMB_ * D_];
__device__ __align__(16) __half g_W1lo[EMB_ * D_];

// ---------------- dynamic smem layout (bytes) ----------------
#define SM_B1S    0                // 64 f
#define SM_LABS   256              // 64 int
#define SM_CSUM   512              // 2 x 640 f -> ends 5632
#define SM_BUF    6144
// stage: Ahi 8K | Alo 8K | Bhi 8K | Blo 8K   (64 rows x 128B each)
#define ALO_OFF   8192
#define BHI_OFF   16384
#define BLO_OFF   24576
#define STAGE_SZ  32768
#define SMEM_TOTAL (SM_BUF + 2 * STAGE_SZ)   // 71680

__device__ __forceinline__ uint32_t smem_u32(const void* p) {
    uint32_t a;
    asm("{ .reg .u64 t; cvta.to.shared.u64 t, %1; cvt.u32.u64 %0, t; }" : "=r"(a) : "l"(p));
    return a;
}
__device__ __forceinline__ uint32_t sw128(uint32_t o) { return o ^ ((o >> 3) & 0x70); }

__device__ __forceinline__ void ldmx4(uint32_t* r, uint32_t addr) {
    asm volatile("ldmatrix.sync.aligned.m8n8.x4.shared.b16 {%0,%1,%2,%3}, [%4];"
                 : "=r"(r[0]), "=r"(r[1]), "=r"(r[2]), "=r"(r[3]) : "r"(addr));
}
__device__ __forceinline__ void mma16816(float* c, const uint32_t* a, uint32_t b0, uint32_t b1) {
    asm volatile("mma.sync.aligned.m16n8k16.row.col.f32.f16.f16.f32 "
                 "{%0,%1,%2,%3}, {%4,%5,%6,%7}, {%8,%9}, {%0,%1,%2,%3};"
                 : "+f"(c[0]), "+f"(c[1]), "+f"(c[2]), "+f"(c[3])
                 : "r"(a[0]), "r"(a[1]), "r"(a[2]), "r"(a[3]), "r"(b0), "r"(b1));
}
__device__ __forceinline__ void cpasync16(uint32_t saddr, const void* gaddr) {
    asm volatile("cp.async.cg.shared.global [%0], [%1], 16;" :: "r"(saddr), "l"(gaddr));
}
__device__ __forceinline__ void bar_sync(int id) {
    asm volatile("bar.sync %0, %1;" :: "r"(id), "r"(NTHR) : "memory");
}
__device__ __forceinline__ void bar_arrive(int id) {
    asm volatile("bar.arrive %0, %1;" :: "r"(id), "r"(NTHR) : "memory");
}

// ---------------------------------------------------------------------------
// Kernel 0: split-convert W1 to fp16 hi/lo
// ---------------------------------------------------------------------------
__global__ void init_kernel(const float* __restrict__ W1) {
    int i4 = blockIdx.x * 256 + threadIdx.x;
    float4 v = *(const float4*)(W1 + (size_t)i4 * 4);
    __half2 h0 = __floats2half2_rn(v.x, v.y);
    __half2 h1 = __floats2half2_rn(v.z, v.w);
    float2 f0 = __half22float2(h0), f1 = __half22float2(h1);
    __half2 l0 = __floats2half2_rn(v.x - f0.x, v.y - f0.y);
    __half2 l1 = __floats2half2_rn(v.z - f1.x, v.w - f1.y);
    uint2 hv, lv;
    hv.x = *(uint32_t*)&h0; hv.y = *(uint32_t*)&h1;
    lv.x = *(uint32_t*)&l0; lv.y = *(uint32_t*)&l1;
    *(uint2*)(g_W1hi + (size_t)i4 * 4) = hv;
    *(uint2*)(g_W1lo + (size_t)i4 * 4) = lv;
}

// ---------------------------------------------------------------------------
// Fused kernel, WARP-SPECIALIZED (R14 skeleton) + m32n32 consumer tiling:
//   warps 0-3 (consumers): bar.sync(full) -> LDSM+MMA only -> bar.arrive(empty)
//       warp tile m32 x n32 (wm = warp&1, wn = warp>>1): -20% LDSM traffic
//   warps 4-7 (producers): B cp.async + A LDG->cvt->STS -> bar.arrive(full)
// 3-term split D = Ahi*Bhi + Ahi*Blo + Alo*Bhi; last CTA per batch runs head.
// ---------------------------------------------------------------------------
__global__ void __launch_bounds__(NTHR, 2)
fused_kernel(const float* __restrict__ data,
             const int*   __restrict__ labels,
             const float* __restrict__ b1,
             const float* __restrict__ Wa1, const float* __restrict__ ba1,
             const float* __restrict__ Wa2, const float* __restrict__ ba2,
             const float* __restrict__ Wf1, const float* __restrict__ bf1,
             const float* __restrict__ Wf2, const float* __restrict__ bf2,
             float* __restrict__ out) {
    extern __shared__ char smem[];
    const uint32_t sb = smem_u32(smem);
    const int tid  = threadIdx.x;
    const int warp = tid >> 5;
    const int lane = tid & 31;
    const int b    = blockIdx.y;
    const int bx   = blockIdx.x;
    const int p0   = bx * TILE_M;

    float* b1s  = (float*)(smem + SM_B1S);
    int*   labs = (int*)  (smem + SM_LABS);
    float* csum = (float*)(smem + SM_CSUM);

    if (tid < EMB_)   b1s[tid]  = b1[tid];
    if (tid < TILE_M) labs[tid] = labels[b * N_ + p0 + tid];
    for (int i = tid; i < 2 * CLN_ * EMB_; i += NTHR) csum[i] = 0.0f;
    __syncthreads();

    float acc[8][4];                   // consumer: [mi*4 + j*2 + s][4]
#pragma unroll
    for (int nt = 0; nt < 8; nt++)
#pragma unroll
        for (int i = 0; i < 4; i++) acc[nt][i] = 0.0f;

    if (warp >= 4) {
        // ================= PRODUCER warps (4-7) =================
        const int tp  = tid - 128;            // 0..127
        const int a_r = tp >> 4;              // A row base
        const int a_q = tp & 15;
        const int b_r = tp >> 3;              // B row base
        const int b_q = tp & 7;
        const float* dbase = data + (size_t)(b * N_ + p0) * D_;

        for (int c = 0; c < NCHUNK; c++) {
            const int si = c & 1;
            if (c >= 2) bar_sync(BAR_EMPTY0 + si);      // consumers freed stage

            const uint32_t bufa = sb + SM_BUF + si * STAGE_SZ;
            char* buf = smem + SM_BUF + si * STAGE_SZ;
            const int kc = c * KC_;

            // B: cp.async from pre-split weights
#pragma unroll
            for (int l = 0; l < 4; l++) {
                int r = b_r + l * 16;
                uint32_t sw = sw128((uint32_t)(r * 128 + b_q * 16));
                cpasync16(bufa + BHI_OFF + sw, g_W1hi + (size_t)r * D_ + kc + b_q * 8);
                cpasync16(bufa + BLO_OFF + sw, g_W1lo + (size_t)r * D_ + kc + b_q * 8);
            }
            asm volatile("cp.async.commit_group;");

            // A: LDG -> split-cvt -> STS
#pragma unroll
            for (int l = 0; l < 8; l++) {
                int r = a_r + l * 8;
                float4 x = *(const float4*)(dbase + (size_t)r * D_ + kc + a_q * 4);
                __half2 h0 = __floats2half2_rn(x.x, x.y);
                __half2 h1 = __floats2half2_rn(x.z, x.w);
                float2 f0 = __half22float2(h0), f1 = __half22float2(h1);
                __half2 l0 = __floats2half2_rn(x.x - f0.x, x.y - f0.y);
                __half2 l1 = __floats2half2_rn(x.z - f1.x, x.w - f1.y);
                uint32_t sw = sw128((uint32_t)(r * 128 + a_q * 8));
                uint2 hv, lv;
                hv.x = *(uint32_t*)&h0; hv.y = *(uint32_t*)&h1;
                lv.x = *(uint32_t*)&l0; lv.y = *(uint32_t*)&l1;
                *(uint2*)(buf + sw)           = hv;
                *(uint2*)(buf + ALO_OFF + sw) = lv;
            }
            asm volatile("cp.async.wait_group 0;");
            asm volatile("membar.cta;");                 // order STS before arrive
            bar_arrive(BAR_FULL0 + si);
        }
    } else {
        // ================= CONSUMER warps (0-3), m32n32 tile =================
        const int wm = warp & 1;          // rows wm*32..+31
        const int wn = warp >> 1;         // cols wn*32..+31
        const uint32_t arow0 = (uint32_t)(wm * 32 + (lane & 15));
        const uint32_t acolb = (uint32_t)((lane >> 4) * 16);
        const uint32_t brow8 = (uint32_t)(((lane >> 4) & 1) * 8 + (lane & 7));
        const uint32_t bkb   = (uint32_t)(((lane >> 3) & 1) * 16);

        for (int c = 0; c < NCHUNK; c++) {
            const int si = c & 1;
            bar_sync(BAR_FULL0 + si);                    // stage ready
            const uint32_t st = sb + SM_BUF + si * STAGE_SZ;
#pragma unroll
            for (int ks = 0; ks < 4; ks++) {
                uint32_t ah[2][4], al[2][4];
#pragma unroll
                for (int mi = 0; mi < 2; mi++) {
                    uint32_t aoff = sw128((arow0 + (uint32_t)(mi * 16)) * 128 +
                                          (uint32_t)(ks * 32) + acolb);
                    ldmx4(ah[mi], st + aoff);
                    ldmx4(al[mi], st + ALO_OFF + aoff);
                }
#pragma unroll
                for (int j = 0; j < 2; j++) {
                    uint32_t bh[4], bl[4];
                    uint32_t boff = sw128((uint32_t)(wn * 32 + j * 16 + (int)brow8) * 128 +
                                          (uint32_t)(ks * 32) + bkb);
                    ldmx4(bh, st + BHI_OFF + boff);
                    ldmx4(bl, st + BLO_OFF + boff);
#pragma unroll
                    for (int mi = 0; mi < 2; mi++) {
                        float* a0 = acc[mi * 4 + j * 2];
                        float* a1 = acc[mi * 4 + j * 2 + 1];
                        mma16816(a0, ah[mi], bh[0], bh[1]);
                        mma16816(a0, ah[mi], bl[0], bl[1]);
                        mma16816(a0, al[mi], bh[0], bh[1]);
                        mma16816(a1, ah[mi], bh[2], bh[3]);
                        mma16816(a1, ah[mi], bl[2], bl[3]);
                        mma16816(a1, al[mi], bh[2], bh[3]);
                    }
                }
            }
            bar_arrive(BAR_EMPTY0 + si);                 // stage free
        }
    }
    __syncthreads();

    // ---- epilogue: bias + ReLU -> e-tile (64 x 66, reuse stage region) ----
    float* etile = (float*)(smem + SM_BUF);
    if (warp < 4) {
        const int wm = warp & 1;
        const int wn = warp >> 1;
        int cq = 2 * (lane & 3);
#pragma unroll
        for (int mi = 0; mi < 2; mi++) {
            int r0 = wm * 32 + mi * 16 + (lane >> 2);
#pragma unroll
            for (int j = 0; j < 2; j++)
#pragma unroll
                for (int s = 0; s < 2; s++) {
                    int col = wn * 32 + j * 16 + s * 8 + cq;
                    float* a = acc[mi * 4 + j * 2 + s];
                    float bv0 = b1s[col], bv1 = b1s[col + 1];
                    etile[r0 * 66 + col]           = fmaxf(a[0] + bv0, 0.0f);
                    etile[r0 * 66 + col + 1]       = fmaxf(a[1] + bv1, 0.0f);
                    etile[(r0 + 8) * 66 + col]     = fmaxf(a[2] + bv0, 0.0f);
                    etile[(r0 + 8) * 66 + col + 1] = fmaxf(a[3] + bv1, 0.0f);
                }
        }
    }
    __syncthreads();

    if (tid < 128) {   // split-row segment reduction, no atomics
        int half = tid >> 6;
        int e    = tid & 63;
        float* cs = csum + half * (CLN_ * EMB_);
        int rbase = half * 32;
        for (int r = 0; r < 32; r++) {
            int row = rbase + r;
            cs[labs[row] * EMB_ + e] += etile[row * 66 + e];
        }
    }
    __syncthreads();

    float* prow = g_part + ((size_t)b * NCTA_X + bx) * PSTRIDE;
    for (int i = tid; i < CLN_ * EMB_; i += NTHR)
        prow[i] = csum[i] + csum[CLN_ * EMB_ + i];
    if (tid < CLN_) {
        int cnt = 0;
        for (int r = 0; r < TILE_M; r++) cnt += (labs[r] == tid);
        prow[640 + tid] = (float)cnt;
    }
    __threadfence();
    __syncthreads();

    // ---- last CTA of this batch runs the head ----
    __shared__ int s_last;
    if (tid == 0) s_last = (atomicAdd(&g_done[b], 1) == NCTA_X - 1) ? 1 : 0;
    __syncthreads();
    if (!s_last) return;
    __threadfence();

    float* hc    = (float*)(smem + SM_BUF);
    float* h     = hc + 656;
    float* u     = h + 640;
    float* score = u + 320;
    float* Avec  = score + 16;
    float* mask  = Avec + 16;
    float* Mv    = mask + 16;
    float* f     = Mv + 64;

    for (int i = tid; i < 650; i += NTHR) {
        float s = 0.0f;
        const float* base = g_part + (size_t)b * NCTA_X * PSTRIDE + i;
#pragma unroll
        for (int j = 0; j < NCTA_X; j++) s += base[j * PSTRIDE];
        hc[i] = s;
    }
    __syncthreads();

    if (tid < EMB_) {
        for (int c = 0; c < CLN_; c++)
            h[c * EMB_ + tid] = hc[c * EMB_ + tid] / fmaxf(hc[640 + c], 1.0f);
    }
    if (tid < CLN_) mask[tid] = (hc[640 + tid] > 0.0f) ? 1.0f : 0.0f;
    __syncthreads();

    if (tid < 32) {
        for (int c = 0; c < CLN_; c++) {
            float s = ba1[tid];
            for (int e = 0; e < EMB_; e++) s += h[c * EMB_ + e] * Wa1[tid * EMB_ + e];
            u[c * 32 + tid] = tanhf(s);
        }
    }
    __syncthreads();

    if (tid < CLN_) {
        float s = ba2[0];
        for (int k = 0; k < 32; k++) s += u[tid * 32 + k] * Wa2[k];
        score[tid] = s;
    }
    __syncthreads();

    if (tid == 0) {
        float xmax = -1e30f;
        for (int c = 0; c < CLN_; c++) {
            float xm = score[c] * mask[c] + (1.0f - 1.0f / (mask[c] + 1e-5f));
            xmax = fmaxf(xmax, xm);
        }
        float ssum = 0.0f;
        for (int c = 0; c < CLN_; c++) {
            float ex = expf(score[c] - xmax) * mask[c];
            Avec[c] = ex;
            ssum += ex;
        }
        for (int c = 0; c < CLN_; c++) Avec[c] /= ssum;
    }
    __syncthreads();

    if (tid < EMB_) {
        float m = 0.0f;
        for (int c = 0; c < CLN_; c++) m += Avec[c] * h[c * EMB_ + tid];
        Mv[tid] = m;
    }
    __syncthreads();

    if (tid < 32) {
        float s = bf1[tid];
        for (int e = 0; e < EMB_; e++) s += Mv[e] * Wf1[tid * EMB_ + e];
        f[tid] = fmaxf(s, 0.0f);
    }
    __syncthreads();

    if (tid == 0) {
        float s = bf2[0];
        for (int k = 0; k < 32; k++) s += f[k] * Wf2[k];
        out[b] = s;
        g_done[b] = 0;      // reset for next graph replay
    }
}

// ---------------------------------------------------------------------------
extern "C" void kernel_launch(void* const* d_in, const int* in_sizes, int n_in,
                              void* d_out, int out_size) {
    const float* data   = (const float*)d_in[0];
    const int*   labels = (const int*)  d_in[1];
    const float* W1     = (const float*)d_in[2];
    const float* b1     = (const float*)d_in[3];
    const float* Wa1    = (const float*)d_in[4];
    const float* ba1    = (const float*)d_in[5];
    const float* Wa2    = (const float*)d_in[6];
    const float* ba2    = (const float*)d_in[7];
    const float* Wf1    = (const float*)d_in[8];
    const float* bf1    = (const float*)d_in[9];
    const float* Wf2    = (const float*)d_in[10];
    const float* bf2    = (const float*)d_in[11];

    cudaFuncSetAttribute(fused_kernel, cudaFuncAttributeMaxDynamicSharedMemorySize,
                         SMEM_TOTAL);

    init_kernel<<<64, 256>>>(W1);
    fused_kernel<<<dim3(NCTA_X, B_), NTHR, SMEM_TOTAL>>>(
        data, labels, b1, Wa1, ba1, Wa2, ba2, Wf1, bf1, Wf2, bf2,
        (float*)d_out);
}

// round 17
// speedup vs baseline: 1.0966x; 1.0459x over previous
#include <cuda_runtime.h>
#include <cuda_fp16.h>
#include <cstdint>

#define B_     8
#define N_     4096
#define D_     1024
#define EMB_   64
#define CLN_   10
#define TILE_M 64
#define KC_    64
#define NCHUNK (D_ / KC_)          // 16
#define NTHR   256                 // 4 consumer + 4 producer warps
#define NCTA_X (N_ / TILE_M)       // 64 CTAs per batch
#define PSTRIDE 656

// named barrier ids
#define BAR_FULL0  1
#define BAR_FULL1  2
#define BAR_EMPTY0 3
#define BAR_EMPTY1 4

// ---------------- device scratch (allocation-free rule) ----------------
__device__ float g_part[B_ * NCTA_X * PSTRIDE];
__device__ int   g_done[B_];                      // zero-init; self-resetting
__device__ __align__(16) __half g_W1hi[EMB_ * D_];
__device__ __align__(16) __half g_W1lo[EMB_ * D_];

// ---------------- dynamic smem layout (bytes) ----------------
#define SM_B1S    0                // 64 f
#define SM_LABS   256              // 64 int
#define SM_CSUM   512              // 2 x 640 f -> ends 5632
#define SM_BUF    6144
// stage: Ahi 8K | Alo 8K | Bhi 8K | Blo 8K   (64 rows x 128B each)
#define ALO_OFF   8192
#define BHI_OFF   16384
#define BLO_OFF   24576
#define STAGE_SZ  32768
#define SMEM_TOTAL (SM_BUF + 2 * STAGE_SZ)   // 71680

__device__ __forceinline__ uint32_t smem_u32(const void* p) {
    uint32_t a;
    asm("{ .reg .u64 t; cvta.to.shared.u64 t, %1; cvt.u32.u64 %0, t; }" : "=r"(a) : "l"(p));
    return a;
}
__device__ __forceinline__ uint32_t sw128(uint32_t o) { return o ^ ((o >> 3) & 0x70); }

__device__ __forceinline__ void ldmx4(uint32_t* r, uint32_t addr) {
    asm volatile("ldmatrix.sync.aligned.m8n8.x4.shared.b16 {%0,%1,%2,%3}, [%4];"
                 : "=r"(r[0]), "=r"(r[1]), "=r"(r[2]), "=r"(r[3]) : "r"(addr));
}
__device__ __forceinline__ void mma16816(float* c, const uint32_t* a, uint32_t b0, uint32_t b1) {
    asm volatile("mma.sync.aligned.m16n8k16.row.col.f32.f16.f16.f32 "
                 "{%0,%1,%2,%3}, {%4,%5,%6,%7}, {%8,%9}, {%0,%1,%2,%3};"
                 : "+f"(c[0]), "+f"(c[1]), "+f"(c[2]), "+f"(c[3])
                 : "r"(a[0]), "r"(a[1]), "r"(a[2]), "r"(a[3]), "r"(b0), "r"(b1));
}
__device__ __forceinline__ void cpasync16(uint32_t saddr, const void* gaddr) {
    asm volatile("cp.async.cg.shared.global [%0], [%1], 16;" :: "r"(saddr), "l"(gaddr));
}
__device__ __forceinline__ void bar_sync(int id) {
    asm volatile("bar.sync %0, %1;" :: "r"(id), "r"(NTHR) : "memory");
}
__device__ __forceinline__ void bar_arrive(int id) {
    asm volatile("bar.arrive %0, %1;" :: "r"(id), "r"(NTHR) : "memory");
}

// ---------------------------------------------------------------------------
// Kernel 0: split-convert W1 to fp16 hi/lo
// ---------------------------------------------------------------------------
__global__ void init_kernel(const float* __restrict__ W1) {
    int i4 = blockIdx.x * 256 + threadIdx.x;
    float4 v = *(const float4*)(W1 + (size_t)i4 * 4);
    __half2 h0 = __floats2half2_rn(v.x, v.y);
    __half2 h1 = __floats2half2_rn(v.z, v.w);
    float2 f0 = __half22float2(h0), f1 = __half22float2(h1);
    __half2 l0 = __floats2half2_rn(v.x - f0.x, v.y - f0.y);
    __half2 l1 = __floats2half2_rn(v.z - f1.x, v.w - f1.y);
    uint2 hv, lv;
    hv.x = *(uint32_t*)&h0; hv.y = *(uint32_t*)&h1;
    lv.x = *(uint32_t*)&l0; lv.y = *(uint32_t*)&l1;
    *(uint2*)(g_W1hi + (size_t)i4 * 4) = hv;
    *(uint2*)(g_W1lo + (size_t)i4 * 4) = lv;
}

// ---------------------------------------------------------------------------
// Fused kernel, WARP-SPECIALIZED (R16 skeleton):
//   consumers (warps 0-3): m32n32 tile, LDSM+MMA only
//   producers (warps 4-7): B cp.async + A cvt/STS from PREFETCHED regs;
//       LDG for chunk c+1 issued before the waits (latency overlapped);
//       membar removed — bar.arrive release / bar.sync acquire ordering.
// 3-term split D = Ahi*Bhi + Ahi*Blo + Alo*Bhi; last CTA per batch runs head.
// ---------------------------------------------------------------------------
__global__ void __launch_bounds__(NTHR, 2)
fused_kernel(const float* __restrict__ data,
             const int*   __restrict__ labels,
             const float* __restrict__ b1,
             const float* __restrict__ Wa1, const float* __restrict__ ba1,
             const float* __restrict__ Wa2, const float* __restrict__ ba2,
             const float* __restrict__ Wf1, const float* __restrict__ bf1,
             const float* __restrict__ Wf2, const float* __restrict__ bf2,
             float* __restrict__ out) {
    extern __shared__ char smem[];
    const uint32_t sb = smem_u32(smem);
    const int tid  = threadIdx.x;
    const int warp = tid >> 5;
    const int lane = tid & 31;
    const int b    = blockIdx.y;
    const int bx   = blockIdx.x;
    const int p0   = bx * TILE_M;

    float* b1s  = (float*)(smem + SM_B1S);
    int*   labs = (int*)  (smem + SM_LABS);
    float* csum = (float*)(smem + SM_CSUM);

    if (tid < EMB_)   b1s[tid]  = b1[tid];
    if (tid < TILE_M) labs[tid] = labels[b * N_ + p0 + tid];
    for (int i = tid; i < 2 * CLN_ * EMB_; i += NTHR) csum[i] = 0.0f;
    __syncthreads();

    float acc[8][4];                   // consumer: [mi*4 + j*2 + s][4]
#pragma unroll
    for (int nt = 0; nt < 8; nt++)
#pragma unroll
        for (int i = 0; i < 4; i++) acc[nt][i] = 0.0f;

    if (warp >= 4) {
        // ================= PRODUCER warps (4-7) =================
        const int tp  = tid - 128;            // 0..127
        const int a_r = tp >> 4;              // A row base (+l*8)
        const int a_q = tp & 15;
        const int b_r = tp >> 3;              // B row base (+l*16)
        const int b_q = tp & 7;
        const float* dbase = data + (size_t)(b * N_ + p0) * D_;

        float4 pre[8];
#pragma unroll
        for (int l = 0; l < 8; l++)           // prefetch chunk 0
            pre[l] = *(const float4*)(dbase + (size_t)(a_r + l * 8) * D_ + a_q * 4);

        for (int c = 0; c < NCHUNK; c++) {
            const int si = c & 1;
            if (c >= 2) bar_sync(BAR_EMPTY0 + si);      // consumers freed stage

            const uint32_t bufa = sb + SM_BUF + si * STAGE_SZ;
            char* buf = smem + SM_BUF + si * STAGE_SZ;
            const int kc = c * KC_;

            // B: cp.async from pre-split weights
#pragma unroll
            for (int l = 0; l < 4; l++) {
                int r = b_r + l * 16;
                uint32_t sw = sw128((uint32_t)(r * 128 + b_q * 16));
                cpasync16(bufa + BHI_OFF + sw, g_W1hi + (size_t)r * D_ + kc + b_q * 8);
                cpasync16(bufa + BLO_OFF + sw, g_W1lo + (size_t)r * D_ + kc + b_q * 8);
            }
            asm volatile("cp.async.commit_group;");

            // A: split-cvt prefetched regs -> STS
#pragma unroll
            for (int l = 0; l < 8; l++) {
                int r = a_r + l * 8;
                float4 x = pre[l];
                __half2 h0 = __floats2half2_rn(x.x, x.y);
                __half2 h1 = __floats2half2_rn(x.z, x.w);
                float2 f0 = __half22float2(h0), f1 = __half22float2(h1);
                __half2 l0 = __floats2half2_rn(x.x - f0.x, x.y - f0.y);
                __half2 l1 = __floats2half2_rn(x.z - f1.x, x.w - f1.y);
                uint32_t sw = sw128((uint32_t)(r * 128 + a_q * 8));
                uint2 hv, lv;
                hv.x = *(uint32_t*)&h0; hv.y = *(uint32_t*)&h1;
                lv.x = *(uint32_t*)&l0; lv.y = *(uint32_t*)&l1;
                *(uint2*)(buf + sw)           = hv;
                *(uint2*)(buf + ALO_OFF + sw) = lv;
            }

            // LDG for next chunk: flies during wait_group + barrier round
            if (c + 1 < NCHUNK) {
                const int kc1 = (c + 1) * KC_;
#pragma unroll
                for (int l = 0; l < 8; l++)
                    pre[l] = *(const float4*)(dbase + (size_t)(a_r + l * 8) * D_ + kc1 + a_q * 4);
            }

            asm volatile("cp.async.wait_group 0;");
            bar_arrive(BAR_FULL0 + si);                  // release: orders STS
        }
    } else {
        // ================= CONSUMER warps (0-3), m32n32 tile =================
        const int wm = warp & 1;          // rows wm*32..+31
        const int wn = warp >> 1;         // cols wn*32..+31
        const uint32_t arow0 = (uint32_t)(wm * 32 + (lane & 15));
        const uint32_t acolb = (uint32_t)((lane >> 4) * 16);
        const uint32_t brow8 = (uint32_t)(((lane >> 4) & 1) * 8 + (lane & 7));
        const uint32_t bkb   = (uint32_t)(((lane >> 3) & 1) * 16);

        for (int c = 0; c < NCHUNK; c++) {
            const int si = c & 1;
            bar_sync(BAR_FULL0 + si);                    // acquire: stage ready
            const uint32_t st = sb + SM_BUF + si * STAGE_SZ;
#pragma unroll
            for (int ks = 0; ks < 4; ks++) {
                uint32_t ah[2][4], al[2][4];
#pragma unroll
                for (int mi = 0; mi < 2; mi++) {
                    uint32_t aoff = sw128((arow0 + (uint32_t)(mi * 16)) * 128 +
                                          (uint32_t)(ks * 32) + acolb);
                    ldmx4(ah[mi], st + aoff);
                    ldmx4(al[mi], st + ALO_OFF + aoff);
                }
#pragma unroll
                for (int j = 0; j < 2; j++) {
                    uint32_t bh[4], bl[4];
                    uint32_t boff = sw128((uint32_t)(wn * 32 + j * 16 + (int)brow8) * 128 +
                                          (uint32_t)(ks * 32) + bkb);
                    ldmx4(bh, st + BHI_OFF + boff);
                    ldmx4(bl, st + BLO_OFF + boff);
#pragma unroll
                    for (int mi = 0; mi < 2; mi++) {
                        float* a0 = acc[mi * 4 + j * 2];
                        float* a1 = acc[mi * 4 + j * 2 + 1];
                        mma16816(a0, ah[mi], bh[0], bh[1]);
                        mma16816(a0, ah[mi], bl[0], bl[1]);
                        mma16816(a0, al[mi], bh[0], bh[1]);
                        mma16816(a1, ah[mi], bh[2], bh[3]);
                        mma16816(a1, ah[mi], bl[2], bl[3]);
                        mma16816(a1, al[mi], bh[2], bh[3]);
                    }
                }
            }
            bar_arrive(BAR_EMPTY0 + si);                 // stage free
        }
    }
    __syncthreads();

    // ---- epilogue: bias + ReLU -> e-tile (64 x 66, reuse stage region) ----
    float* etile = (float*)(smem + SM_BUF);
    if (warp < 4) {
        const int wm = warp & 1;
        const int wn = warp >> 1;
        int cq = 2 * (lane & 3);
#pragma unroll
        for (int mi = 0; mi < 2; mi++) {
            int r0 = wm * 32 + mi * 16 + (lane >> 2);
#pragma unroll
            for (int j = 0; j < 2; j++)
#pragma unroll
                for (int s = 0; s < 2; s++) {
                    int col = wn * 32 + j * 16 + s * 8 + cq;
                    float* a = acc[mi * 4 + j * 2 + s];
                    float bv0 = b1s[col], bv1 = b1s[col + 1];
                    etile[r0 * 66 + col]           = fmaxf(a[0] + bv0, 0.0f);
                    etile[r0 * 66 + col + 1]       = fmaxf(a[1] + bv1, 0.0f);
                    etile[(r0 + 8) * 66 + col]     = fmaxf(a[2] + bv0, 0.0f);
                    etile[(r0 + 8) * 66 + col + 1] = fmaxf(a[3] + bv1, 0.0f);
                }
        }
    }
    __syncthreads();

    if (tid < 128) {   // split-row segment reduction, no atomics
        int half = tid >> 6;
        int e    = tid & 63;
        float* cs = csum + half * (CLN_ * EMB_);
        int rbase = half * 32;
        for (int r = 0; r < 32; r++) {
            int row = rbase + r;
            cs[labs[row] * EMB_ + e] += etile[row * 66 + e];
        }
    }
    __syncthreads();

    float* prow = g_part + ((size_t)b * NCTA_X + bx) * PSTRIDE;
    for (int i = tid; i < CLN_ * EMB_; i += NTHR)
        prow[i] = csum[i] + csum[CLN_ * EMB_ + i];
    if (tid < CLN_) {
        int cnt = 0;
        for (int r = 0; r < TILE_M; r++) cnt += (labs[r] == tid);
        prow[640 + tid] = (float)cnt;
    }
    __threadfence();
    __syncthreads();

    // ---- last CTA of this batch runs the head ----
    __shared__ int s_last;
    if (tid == 0) s_last = (atomicAdd(&g_done[b], 1) == NCTA_X - 1) ? 1 : 0;
    __syncthreads();
    if (!s_last) return;
    __threadfence();

    float* hc    = (float*)(smem + SM_BUF);
    float* h     = hc + 656;
    float* u     = h + 640;
    float* score = u + 320;
    float* Avec  = score + 16;
    float* mask  = Avec + 16;
    float* Mv    = mask + 16;
    float* f     = Mv + 64;

    for (int i = tid; i < 650; i += NTHR) {
        float s = 0.0f;
        const float* base = g_part + (size_t)b * NCTA_X * PSTRIDE + i;
#pragma unroll
        for (int j = 0; j < NCTA_X; j++) s += base[j * PSTRIDE];
        hc[i] = s;
    }
    __syncthreads();

    if (tid < EMB_) {
        for (int c = 0; c < CLN_; c++)
            h[c * EMB_ + tid] = hc[c * EMB_ + tid] / fmaxf(hc[640 + c], 1.0f);
    }
    if (tid < CLN_) mask[tid] = (hc[640 + tid] > 0.0f) ? 1.0f : 0.0f;
    __syncthreads();

    if (tid < 32) {
        for (int c = 0; c < CLN_; c++) {
            float s = ba1[tid];
            for (int e = 0; e < EMB_; e++) s += h[c * EMB_ + e] * Wa1[tid * EMB_ + e];
            u[c * 32 + tid] = tanhf(s);
        }
    }
    __syncthreads();

    if (tid < CLN_) {
        float s = ba2[0];
        for (int k = 0; k < 32; k++) s += u[tid * 32 + k] * Wa2[k];
        score[tid] = s;
    }
    __syncthreads();

    if (tid == 0) {
        float xmax = -1e30f;
        for (int c = 0; c < CLN_; c++) {
            float xm = score[c] * mask[c] + (1.0f - 1.0f / (mask[c] + 1e-5f));
            xmax = fmaxf(xmax, xm);
        }
        float ssum = 0.0f;
        for (int c = 0; c < CLN_; c++) {
            float ex = expf(score[c] - xmax) * mask[c];
            Avec[c] = ex;
            ssum += ex;
        }
        for (int c = 0; c < CLN_; c++) Avec[c] /= ssum;
    }
    __syncthreads();

    if (tid < EMB_) {
        float m = 0.0f;
        for (int c = 0; c < CLN_; c++) m += Avec[c] * h[c * EMB_ + tid];
        Mv[tid] = m;
    }
    __syncthreads();

    if (tid < 32) {
        float s = bf1[tid];
        for (int e = 0; e < EMB_; e++) s += Mv[e] * Wf1[tid * EMB_ + e];
        f[tid] = fmaxf(s, 0.0f);
    }
    __syncthreads();

    if (tid == 0) {
        float s = bf2[0];
        for (int k = 0; k < 32; k++) s += f[k] * Wf2[k];
        out[b] = s;
        g_done[b] = 0;      // reset for next graph replay
    }
}

// ---------------------------------------------------------------------------
extern "C" void kernel_launch(void* const* d_in, const int* in_sizes, int n_in,
                              void* d_out, int out_size) {
    const float* data   = (const float*)d_in[0];
    const int*   labels = (const int*)  d_in[1];
    const float* W1     = (const float*)d_in[2];
    const float* b1     = (const float*)d_in[3];
    const float* Wa1    = (const float*)d_in[4];
    const float* ba1    = (const float*)d_in[5];
    const float* Wa2    = (const float*)d_in[6];
    const float* ba2    = (const float*)d_in[7];
    const float* Wf1    = (const float*)d_in[8];
    const float* bf1    = (const float*)d_in[9];
    const float* Wf2    = (const float*)d_in[10];
    const float* bf2    = (const float*)d_in[11];

    cudaFuncSetAttribute(fused_kernel, cudaFuncAttributeMaxDynamicSharedMemorySize,
                         SMEM_TOTAL);

    init_kernel<<<64, 256>>>(W1);
    fused_kernel<<<dim3(NCTA_X, B_), NTHR, SMEM_TOTAL>>>(
        data, labels, b1, Wa1, ba1, Wa2, ba2, Wf1, bf1, Wf2, bf2,
        (float*)d_out);
}